// round 6
// baseline (speedup 1.0000x reference)
#include <cuda_runtime.h>
#include <cuda_bf16.h>

// CovarianceResidualError, fused persistent kernel, SM-balanced grid:
//   a_i = graph_emb[i,0];  ACC_j = sum_i e_ij*a_i;  SE_j = sum_i e_ij;  SA = sum_i a_i
//   out = -sum_j |ACC_j - SA*SE_j/N|
//
// 592 CTAs = 148 SMs x 4 (exactly 4 resident CTAs per SM -> no per-SM work
// imbalance; previous 512-CTA grid left an ~8us straggler tail).
// Phase 1: each CTA handles ~221 rows, writes transposed float2(acc,se)
//          partials at g_pT[col*NBLK + bid].
// Grid barrier via counter; blocks 0..31 do the coalesced column reduce and
// the last-arriving one does SA + the deterministic final |.| sum.

#define NROWS 131072
#define OCOLS 256
#define DCOLS 128
#define NBLK  592                          // 148 * 4
#define NRED  32                           // reducer blocks (8 columns each)
#define COLV4 (NBLK / 2)                   // 296 float4 per column

__device__ float2 g_pT[OCOLS * NBLK];      // [col][block] -> (acc, se)
__device__ float  g_psa[NBLK];
__device__ float  g_colA[OCOLS];
__device__ float  g_colS[OCOLS];
__device__ volatile unsigned int g_c1 = 0; // phase-1 completion counter
__device__ unsigned int g_c2 = 0;          // reducer ticket

__global__ void __launch_bounds__(256, 4)
cov_fused_kernel(const float* __restrict__ ge, const float4* __restrict__ err4,
                 float* __restrict__ out)
{
    __shared__ float a_sh[224];
    __shared__ float red[4 * OCOLS];
    __shared__ unsigned int s_ticket;

    const int tid = threadIdx.x;
    const int tx  = tid & 63;      // column group: columns 4*tx .. 4*tx+3
    const int ty  = tid >> 6;      // row phase 0..3
    const int bid = blockIdx.x;

    // Balanced row range for this CTA (221 or 222 rows)
    const int r0 = (int)(((long long)bid * NROWS) / NBLK);
    const int r1 = (int)(((long long)(bid + 1) * NROWS) / NBLK);
    const int nr = r1 - r0;

    // ================= Phase 1: per-block partials =================
    float a_mine = 0.f;
    if (tid < nr) a_mine = ge[(size_t)(r0 + tid) * DCOLS];
    if (tid < 224) a_sh[tid] = a_mine;      // zero beyond nr (a_mine init 0)
    __syncthreads();

    float4 acc = make_float4(0.f, 0.f, 0.f, 0.f);
    float4 se  = make_float4(0.f, 0.f, 0.f, 0.f);

    #pragma unroll 8
    for (int r = ty; r < nr; r += 4) {
        const float4 e = err4[(size_t)(r0 + r) * (OCOLS / 4) + tx];
        const float  a = a_sh[r];
        acc.x = fmaf(e.x, a, acc.x); acc.y = fmaf(e.y, a, acc.y);
        acc.z = fmaf(e.z, a, acc.z); acc.w = fmaf(e.w, a, acc.w);
        se.x += e.x; se.y += e.y; se.z += e.z; se.w += e.w;
    }

    // Reduce the 4 row phases (deterministic, via shared), pack (acc,se)
    __syncthreads();
    red[ty * OCOLS + 4 * tx + 0] = acc.x;
    red[ty * OCOLS + 4 * tx + 1] = acc.y;
    red[ty * OCOLS + 4 * tx + 2] = acc.z;
    red[ty * OCOLS + 4 * tx + 3] = acc.w;
    __syncthreads();
    const float accTot =
        red[tid] + red[OCOLS + tid] + red[2 * OCOLS + tid] + red[3 * OCOLS + tid];
    __syncthreads();
    red[ty * OCOLS + 4 * tx + 0] = se.x;
    red[ty * OCOLS + 4 * tx + 1] = se.y;
    red[ty * OCOLS + 4 * tx + 2] = se.z;
    red[ty * OCOLS + 4 * tx + 3] = se.w;
    __syncthreads();
    const float seTot =
        red[tid] + red[OCOLS + tid] + red[2 * OCOLS + tid] + red[3 * OCOLS + tid];

    // Transposed partial store: column 'tid', block 'bid'
    g_pT[(size_t)tid * NBLK + bid] = make_float2(accTot, seTot);

    // Block partial of SA: fixed-shape tree over 256 slots (zeros beyond nr)
    __syncthreads();
    red[tid] = a_mine;
    __syncthreads();
    #pragma unroll
    for (int st = 128; st > 0; st >>= 1) {
        if (tid < st) red[tid] += red[tid + st];
        __syncthreads();
    }
    if (tid == 0) {
        g_psa[bid] = red[0];
        __threadfence();
        atomicAdd((unsigned int*)&g_c1, 1u);
    }

    if (bid >= NRED) return;

    // ================= grid barrier (spin with backoff) =================
    if (tid == 0) {
        while (g_c1 != NBLK) __nanosleep(64);
    }
    __syncthreads();
    __threadfence();

    // ================= Phase 2: contiguous column reduce =================
    // One warp per column: column c = 296 contiguous float4 (L2-warm).
    const int cc = tid >> 5;            // warp 0..7 -> column within group
    const int t  = tid & 31;            // lane
    const int c  = bid * 8 + cc;
    const float4* p4 = (const float4*)g_pT;

    float a = 0.f, s = 0.f;
    #pragma unroll
    for (int k = t; k < COLV4; k += 32) {
        const float4 v = p4[(size_t)c * COLV4 + k];
        a += v.x + v.z;                 // two (acc,se) pairs per float4
        s += v.y + v.w;
    }
    #pragma unroll
    for (int off = 16; off > 0; off >>= 1) {
        a += __shfl_down_sync(0xffffffffu, a, off);
        s += __shfl_down_sync(0xffffffffu, s, off);
    }
    if (t == 0) {
        g_colA[c] = a;
        g_colS[c] = s;
    }

    if (tid == 0) {
        __threadfence();
        s_ticket = atomicAdd(&g_c2, 1u);
    }
    __syncthreads();

    // ================= Phase 3: last reducer does final scalar =================
    if (s_ticket == NRED - 1) {
        __threadfence();
        // SA over 592 block partials (fixed-shape tree in 'red')
        float v = g_psa[tid] + g_psa[tid + 256];
        if (tid < NBLK - 512) v += g_psa[tid + 512];
        red[tid] = v;
        __syncthreads();
        #pragma unroll
        for (int st = 128; st > 0; st >>= 1) {
            if (tid < st) red[tid] += red[tid + st];
            __syncthreads();
        }
        const float k = red[0] * (1.0f / (float)NROWS);
        __syncthreads();

        red[tid] = fabsf(g_colA[tid] - k * g_colS[tid]);
        __syncthreads();
        #pragma unroll
        for (int st = 128; st > 0; st >>= 1) {
            if (tid < st) red[tid] += red[tid + st];
            __syncthreads();
        }
        if (tid == 0) {
            out[0] = -red[0];
            g_c2 = 0;                         // reset for next graph replay
            *(unsigned int*)&g_c1 = 0;
            __threadfence();
        }
    }
}

extern "C" void kernel_launch(void* const* d_in, const int* in_sizes, int n_in,
                              void* d_out, int out_size)
{
    const float* ge  = nullptr;   // graph_emb (N x 128)
    const float* err = nullptr;   // errors    (N x 256)
    for (int i = 0; i < n_in; ++i) {
        if (in_sizes[i] == NROWS * DCOLS) ge  = (const float*)d_in[i];
        else if (in_sizes[i] == NROWS * OCOLS) err = (const float*)d_in[i];
    }

    cov_fused_kernel<<<NBLK, 256>>>(ge, (const float4*)err, (float*)d_out);
}

// round 7
// speedup vs baseline: 1.0086x; 1.0086x over previous
#include <cuda_runtime.h>
#include <cuda_bf16.h>

// CovarianceResidualError, fused persistent kernel, wide phase-2:
//   a_i = graph_emb[i,0];  ACC_j = sum_i e_ij*a_i;  SE_j = sum_i e_ij;  SA = sum_i a_i
//   out = -sum_j |ACC_j - SA*SE_j/N|
//
// Phase 1 (512 blocks x 256 thr): R5-proven chunked streaming loop; partials
//   written TRANSPOSED as float2(acc,se) at g_pT[col*NB + block].
// Grid barrier via counter (all 512 CTAs resident at occupancy 4).
// Phase 2: blocks 0..255 each reduce ONE column (4KB contiguous, one float4
//   per thread -> full-grid parallelism, ~1MB issued at once).
// Phase 3: last-arriving block (ticket) does SA + deterministic |.| sum.

#define NROWS 131072
#define OCOLS 256
#define DCOLS 128
#define NB 512
#define ROWS_PER_BLK (NROWS / NB)          // 256
#define CHUNK 64
#define NCHUNK (ROWS_PER_BLK / CHUNK)      // 4

__device__ float2 g_pT[OCOLS * NB];        // [col][block] -> (acc, se)
__device__ float  g_psa[NB];
__device__ float  g_colA[OCOLS];
__device__ float  g_colS[OCOLS];
__device__ volatile unsigned int g_c1 = 0; // phase-1 completion counter
__device__ unsigned int g_c2 = 0;          // phase-2 ticket

__global__ void __launch_bounds__(256, 4)
cov_fused_kernel(const float* __restrict__ ge, const float4* __restrict__ err4,
                 float* __restrict__ out)
{
    __shared__ float a_sh[CHUNK];
    __shared__ float red[4 * OCOLS];
    __shared__ float shS[OCOLS];
    __shared__ unsigned int s_ticket;

    const int tid = threadIdx.x;
    const int tx  = tid & 63;      // column group: columns 4*tx .. 4*tx+3
    const int ty  = tid >> 6;      // row phase 0..3
    const int bid = blockIdx.x;
    const int row0 = bid * ROWS_PER_BLK;

    // ================= Phase 1: per-block partials (R5-proven) =================
    float4 acc = make_float4(0.f, 0.f, 0.f, 0.f);
    float4 se  = make_float4(0.f, 0.f, 0.f, 0.f);
    float  suma = 0.f;

    float a_next = 0.f;
    if (tid < CHUNK)
        a_next = ge[(size_t)(row0 + tid) * DCOLS];

    for (int c = 0; c < NCHUNK; ++c) {
        const int base = row0 + c * CHUNK;
        __syncthreads();
        if (tid < CHUNK) { a_sh[tid] = a_next; suma += a_next; }
        __syncthreads();
        if (tid < CHUNK && (c + 1) < NCHUNK)
            a_next = ge[(size_t)(base + CHUNK + tid) * DCOLS];

        #pragma unroll
        for (int r = ty; r < CHUNK; r += 4) {
            const float4 e = err4[(size_t)(base + r) * (OCOLS / 4) + tx];
            const float  a = a_sh[r];
            acc.x = fmaf(e.x, a, acc.x); acc.y = fmaf(e.y, a, acc.y);
            acc.z = fmaf(e.z, a, acc.z); acc.w = fmaf(e.w, a, acc.w);
            se.x += e.x; se.y += e.y; se.z += e.z; se.w += e.w;
        }
    }

    // Reduce the 4 row phases (deterministic, via shared), pack (acc,se)
    __syncthreads();
    red[ty * OCOLS + 4 * tx + 0] = acc.x;
    red[ty * OCOLS + 4 * tx + 1] = acc.y;
    red[ty * OCOLS + 4 * tx + 2] = acc.z;
    red[ty * OCOLS + 4 * tx + 3] = acc.w;
    __syncthreads();
    const float accTot =
        red[tid] + red[OCOLS + tid] + red[2 * OCOLS + tid] + red[3 * OCOLS + tid];
    __syncthreads();
    red[ty * OCOLS + 4 * tx + 0] = se.x;
    red[ty * OCOLS + 4 * tx + 1] = se.y;
    red[ty * OCOLS + 4 * tx + 2] = se.z;
    red[ty * OCOLS + 4 * tx + 3] = se.w;
    __syncthreads();
    const float seTot =
        red[tid] + red[OCOLS + tid] + red[2 * OCOLS + tid] + red[3 * OCOLS + tid];

    // Transposed partial store: column 'tid', block 'bid'
    g_pT[(size_t)tid * NB + bid] = make_float2(accTot, seTot);

    // Block partial of SA (fixed order over 64 chunk-sums)
    __syncthreads();
    if (tid < CHUNK) red[tid] = suma;
    __syncthreads();
    if (tid == 0) {
        float s = 0.f;
        #pragma unroll
        for (int i = 0; i < CHUNK; ++i) s += red[i];
        g_psa[bid] = s;
        __threadfence();
        atomicAdd((unsigned int*)&g_c1, 1u);
    }

    if (bid >= OCOLS) return;

    // ================= grid barrier (spin with backoff) =================
    if (tid == 0) {
        while (g_c1 != NB) __nanosleep(64);
    }
    __syncthreads();
    __threadfence();

    // ================= Phase 2: one column per block, one float4/thread ======
    // Column 'bid' = 512 contiguous float2 = 256 float4 (coalesced).
    const float4 v = ((const float4*)g_pT)[(size_t)bid * (NB / 2) + tid];
    float a = v.x + v.z;            // two (acc,se) pairs per float4
    float s = v.y + v.w;

    // Fixed-shape block tree over 256 lanes (a and s together)
    red[tid] = a;
    shS[tid] = s;
    __syncthreads();
    #pragma unroll
    for (int st = 128; st > 0; st >>= 1) {
        if (tid < st) {
            red[tid] += red[tid + st];
            shS[tid] += shS[tid + st];
        }
        __syncthreads();
    }
    if (tid == 0) {
        g_colA[bid] = red[0];
        g_colS[bid] = shS[0];
        __threadfence();
        s_ticket = atomicAdd(&g_c2, 1u);
    }
    __syncthreads();

    // ================= Phase 3: last block does final scalar =================
    if (s_ticket == OCOLS - 1) {
        __threadfence();
        // SA over 512 block partials (fixed-shape tree)
        red[tid] = g_psa[tid] + g_psa[tid + 256];
        __syncthreads();
        #pragma unroll
        for (int st = 128; st > 0; st >>= 1) {
            if (tid < st) red[tid] += red[tid + st];
            __syncthreads();
        }
        const float k = red[0] * (1.0f / (float)NROWS);
        __syncthreads();

        red[tid] = fabsf(g_colA[tid] - k * g_colS[tid]);
        __syncthreads();
        #pragma unroll
        for (int st = 128; st > 0; st >>= 1) {
            if (tid < st) red[tid] += red[tid + st];
            __syncthreads();
        }
        if (tid == 0) {
            out[0] = -red[0];
            g_c2 = 0;                         // reset for next graph replay
            *(unsigned int*)&g_c1 = 0;
            __threadfence();
        }
    }
}

extern "C" void kernel_launch(void* const* d_in, const int* in_sizes, int n_in,
                              void* d_out, int out_size)
{
    const float* ge  = nullptr;   // graph_emb (N x 128)
    const float* err = nullptr;   // errors    (N x 256)
    for (int i = 0; i < n_in; ++i) {
        if (in_sizes[i] == NROWS * DCOLS) ge  = (const float*)d_in[i];
        else if (in_sizes[i] == NROWS * OCOLS) err = (const float*)d_in[i];
    }

    cov_fused_kernel<<<NB, 256>>>(ge, (const float4*)err, (float*)d_out);
}